// round 16
// baseline (speedup 1.0000x reference)
#include <cuda_runtime.h>

#define CC    10
#define NBIN  49
#define HH    34
#define WW    34
#define HW    (HH * WW)          // 1156
#define KDIM  (CC * NBIN)        // 490
#define NMAX  30000
#define BLK   512
#define TILES 4
#define KPAD  512
#define NPADMAX (NMAX + 128)
#define SLC   (NBIN * HW)        // 56644
#define RSTR  12                 // 48B records
#define SMEMB (HW * RSTR * 4)    // 55488 B dynamic smem
#define PREPB ((3 * SLC + 255) / 256)   // 664 blocks for the prep part

// Scratch (static device allocations are allowed)
__device__ float  g_out_t[KPAD * NPADMAX];   // [k][n], runtime pitch NP
__device__ float  g_ftr[NBIN * HW * RSTR];   // [bin][pos][c0..9,pad2]
__device__ float4 g_ax[14 * NMAX * 2];       // [slot 0..13][n] x 2 float4:
                                             // {W0,W1,W2,C0},{C1,C2,cnt,A0f}
                                             // slot 0-6 = Y(ph), 7-13 = X(pw)

// ---------------------------------------------------------------------------
// Kernel A (fused): blocks [0, PREPB) do the ft->records transpose;
// blocks [PREPB, ...) precompute per-(roi, axis, p) weight records using the
// full reference logic (handles interior AND edge rois uniformly).
// ---------------------------------------------------------------------------
__global__ void k_pre(const float* __restrict__ ft,
                      const float* __restrict__ rois, int N) {
    if (blockIdx.x < PREPB) {
        // ---- prep: ft (C*49,34,34) -> 48B channel-interleaved records ----
        int t = blockIdx.x * 256 + threadIdx.x;      // over 3*49*1156
        if (t >= 3 * SLC) return;
        int g   = t / SLC;
        int idx = t - g * SLC;                       // = bin*HW + p
        const float* s = ft + idx;
        float* d = g_ftr + idx * RSTR;
        if (g == 0) {
            float4 v;
            v.x = s[0 * SLC]; v.y = s[1 * SLC]; v.z = s[2 * SLC]; v.w = s[3 * SLC];
            *reinterpret_cast<float4*>(d + 0) = v;
        } else if (g == 1) {
            float4 v;
            v.x = s[4 * SLC]; v.y = s[5 * SLC]; v.z = s[6 * SLC]; v.w = s[7 * SLC];
            *reinterpret_cast<float4*>(d + 4) = v;
        } else {
            float2 v;
            v.x = s[8 * SLC]; v.y = s[9 * SLC];
            *reinterpret_cast<float2*>(d + 8) = v;
        }
        return;
    }

    // ---- axis precompute: one thread per (slot, n), slot = axis*7 + p ----
    int t = (blockIdx.x - PREPB) * 256 + threadIdx.x;   // over 14*N
    if (t >= 14 * N) return;
    int slot = t / N;
    int n    = t - slot * N;
    int isX  = (slot >= 7);
    int p    = isX ? slot - 7 : slot;

    float rs = __ldg(rois + n * 5 + (isX ? 1 : 2)) * 0.125f;
    float re = __ldg(rois + n * 5 + (isX ? 3 : 4)) * 0.125f;
    float r = re - rs; r = (r > 0.1f) ? r : 0.1f;
    float bs  = r * (1.f / 7.f);
    float sub = bs * 0.25f;
    float start = floorf(rs + (float)p * bs);
    int A0 = (int)fminf(fmaxf(start, 0.f), 31.f);
    float A0f = (float)A0;

    float W0 = 0.f, W1 = 0.f, W2 = 0.f;
    float C0 = 0.f, C1 = 0.f, C2 = 0.f;
    float cnt = 0.f;
#pragma unroll
    for (int i = 0; i < 4; i++) {
        float h = start + ((float)i + 0.5f) * sub;
        bool ok = (h > -1.f) && (h < 34.f);
        float y1f = floorf(h), y2f = ceilf(h);
        bool v1 = (y1f >= 0.f) && (y1f < 34.f);
        bool v2 = (y2f >= 0.f) && (y2f < 34.f);
        float y1c = fminf(fmaxf(y1f, 0.f), 33.f);
        float y2c = fminf(fmaxf(y2f, 0.f), 33.f);
        float d = h - y1c;
        int r1 = (int)y1c - A0;
        int r2 = (int)y2c - A0;
        float okf = ok ? 1.f : 0.f;
        cnt += okf;
        float a = okf * (1.f - d), b = okf * d;
        W0 += ((r1 == 0) ? a : 0.f) + ((r2 == 0) ? b : 0.f);
        W1 += ((r1 == 1) ? a : 0.f) + ((r2 == 1) ? b : 0.f);
        W2 += ((r1 == 2) ? a : 0.f) + ((r2 == 2) ? b : 0.f);
        // correction factor: Y axis uses (v1||v2), X axis uses (!v1)||(!v2)
        bool sel = isX ? ((!v1) || (!v2)) : (v1 || v2);
        float c = (ok && sel) ? (1.f - d) : 0.f;
        C0 += (r1 == 0) ? c : 0.f;
        C1 += (r1 == 1) ? c : 0.f;
        C2 += (r1 == 2) ? c : 0.f;
    }
    float4* dst = g_ax + (slot * N + n) * 2;
    dst[0] = make_float4(W0, W1, W2, C0);
    dst[1] = make_float4(C1, C2, cnt, A0f);
}

// ---------------------------------------------------------------------------
// Kernel B: one block = (bin, 4 roi-tiles of 512), grid (15, 49), 3 CTAs/SM.
// Unified path: assemble W9 from precomputed axis records, gather, store.
// ---------------------------------------------------------------------------
__global__ __launch_bounds__(BLK, 3) void k_roi(int N, int NP) {
    extern __shared__ float smR[];   // [pos][12]
    const int bin = blockIdx.y;

    {   // stage: contiguous float4 copy, conflict-free
        const float4* s = reinterpret_cast<const float4*>(g_ftr + bin * HW * RSTR);
        float4* d = reinterpret_cast<float4*>(smR);
        for (int i = threadIdx.x; i < HW * (RSTR / 4); i += BLK) d[i] = s[i];
    }
    __syncthreads();

    const int ph = bin / 7, pw = bin % 7;
    const float4* yrec_base = g_ax + (size_t)(ph)     * N * 2;
    const float4* xrec_base = g_ax + (size_t)(7 + pw) * N * 2;

#pragma unroll 1
    for (int tile = 0; tile < TILES; tile++) {
        const int n = (blockIdx.x * TILES + tile) * BLK + threadIdx.x;
        if (n >= N) break;

        float4 ya = __ldg(yrec_base + n * 2 + 0);   // WY0,WY1,WY2,CY0
        float4 yb = __ldg(yrec_base + n * 2 + 1);   // CY1,CY2,cntY,Y0f
        float4 xa = __ldg(xrec_base + n * 2 + 0);   // WX0,WX1,WX2,CX0
        float4 xb = __ldg(xrec_base + n * 2 + 1);   // CX1,CX2,cntX,X0f

        float cnt = yb.z * xb.z;
        float inv = (cnt > 0.f) ? (1.f / cnt) : 1.f;
        float wy0 = ya.x * inv, wy1 = ya.y * inv, wy2 = ya.z * inv;
        float cy0 = ya.w * inv, cy1 = yb.x * inv, cy2 = yb.y * inv;

        float W00 = fmaf(wy0, xa.x, -cy0 * xa.w);
        float W01 = fmaf(wy0, xa.y, -cy0 * xb.x);
        float W02 = fmaf(wy0, xa.z, -cy0 * xb.y);
        float W10 = fmaf(wy1, xa.x, -cy1 * xa.w);
        float W11 = fmaf(wy1, xa.y, -cy1 * xb.x);
        float W12 = fmaf(wy1, xa.z, -cy1 * xb.y);
        float W20 = fmaf(wy2, xa.x, -cy2 * xa.w);
        float W21 = fmaf(wy2, xa.y, -cy2 * xb.x);
        float W22 = fmaf(wy2, xa.z, -cy2 * xb.y);

        bool colx = (xa.z != 0.f) || (xb.y != 0.f);  // WX2 or CX2
        bool rowx = (ya.z != 0.f) || (yb.y != 0.f);  // WY2 or CY2

        const int Y0 = (int)yb.w, X0 = (int)xb.w;
        const int pbase = Y0 * WW + X0;

        float a0=0.f,a1=0.f,a2=0.f,a3=0.f,a4=0.f,a5=0.f,a6=0.f,a7=0.f,a8=0.f,a9=0.f;

#define TEXEL(WGT, P) do {                                                  \
            const float* _t = smR + (P) * RSTR;                             \
            float4 u0 = *reinterpret_cast<const float4*>(_t);               \
            float4 u1 = *reinterpret_cast<const float4*>(_t + 4);           \
            float2 u2 = *reinterpret_cast<const float2*>(_t + 8);           \
            a0 = fmaf((WGT), u0.x, a0); a1 = fmaf((WGT), u0.y, a1);         \
            a2 = fmaf((WGT), u0.z, a2); a3 = fmaf((WGT), u0.w, a3);         \
            a4 = fmaf((WGT), u1.x, a4); a5 = fmaf((WGT), u1.y, a5);         \
            a6 = fmaf((WGT), u1.z, a6); a7 = fmaf((WGT), u1.w, a7);         \
            a8 = fmaf((WGT), u2.x, a8); a9 = fmaf((WGT), u2.y, a9);         \
        } while (0)

        TEXEL(W00, pbase);
        TEXEL(W01, pbase + 1);
        TEXEL(W10, pbase + WW);
        TEXEL(W11, pbase + WW + 1);
        if (colx) { TEXEL(W02, pbase + 2); TEXEL(W12, pbase + WW + 2); }
        if (rowx) { TEXEL(W20, pbase + 2 * WW); TEXEL(W21, pbase + 2 * WW + 1); }
        if (colx && rowx) { TEXEL(W22, pbase + 2 * WW + 2); }
#undef TEXEL

        g_out_t[(0 * NBIN + bin) * NP + n] = a0;
        g_out_t[(1 * NBIN + bin) * NP + n] = a1;
        g_out_t[(2 * NBIN + bin) * NP + n] = a2;
        g_out_t[(3 * NBIN + bin) * NP + n] = a3;
        g_out_t[(4 * NBIN + bin) * NP + n] = a4;
        g_out_t[(5 * NBIN + bin) * NP + n] = a5;
        g_out_t[(6 * NBIN + bin) * NP + n] = a6;
        g_out_t[(7 * NBIN + bin) * NP + n] = a7;
        g_out_t[(8 * NBIN + bin) * NP + n] = a8;
        g_out_t[(9 * NBIN + bin) * NP + n] = a9;
    }
}

// ---------------------------------------------------------------------------
// Kernel C: transpose scratch[k][n] -> out[n][k]. Tile 32k x 128n, 256 thr.
// Loads UNGUARDED (k padded to KPAD, n padded to pitch NP), MLP=4.
// ---------------------------------------------------------------------------
__global__ __launch_bounds__(256) void k_transpose_out(float* __restrict__ out,
                                                       int N, int NP) {
    __shared__ float tile[32][133];
    const int n0 = blockIdx.x * 128;
    const int k0 = blockIdx.y * 32;
    const int tx = threadIdx.x & 31;
    const int ty = threadIdx.x >> 5;

#pragma unroll
    for (int i = 0; i < 4; i++) {
        int k = k0 + ty + 8 * i;
        float4 v = *reinterpret_cast<const float4*>(&g_out_t[(size_t)k * NP + n0 + tx * 4]);
        tile[ty + 8 * i][tx * 4 + 0] = v.x;
        tile[ty + 8 * i][tx * 4 + 1] = v.y;
        tile[ty + 8 * i][tx * 4 + 2] = v.z;
        tile[ty + 8 * i][tx * 4 + 3] = v.w;
    }
    __syncthreads();

    const int sx = threadIdx.x & 15;
    const int sy = threadIdx.x >> 4;
    const int k  = k0 + sx * 2;
    if (k < KDIM) {
#pragma unroll
        for (int i = 0; i < 8; i++) {
            int n = n0 + sy + 16 * i;
            if (n < N) {
                float2 v;
                v.x = tile[sx * 2 + 0][sy + 16 * i];
                v.y = tile[sx * 2 + 1][sy + 16 * i];
                *reinterpret_cast<float2*>(&out[(size_t)n * KDIM + k]) = v;
            }
        }
    }
}

// ---------------------------------------------------------------------------
extern "C" void kernel_launch(void* const* d_in, const int* in_sizes, int n_in,
                              void* d_out, int out_size) {
    const float* ft   = (const float*)d_in[0];
    const float* rois = (const float*)d_in[1];
    float*       out  = (float*)d_out;
    int N = in_sizes[1] / 5;
    if (N > NMAX) N = NMAX;
    if (N <= 0) return;
    int NP = (N + 127) & ~127;

    cudaFuncSetAttribute(k_roi, cudaFuncAttributeMaxDynamicSharedMemorySize, SMEMB);

    int axisb = (14 * N + 255) / 256;
    k_pre<<<PREPB + axisb, 256>>>(ft, rois, N);

    dim3 gb((N + BLK * TILES - 1) / (BLK * TILES), NBIN);
    k_roi<<<gb, BLK, SMEMB>>>(N, NP);

    dim3 gc(NP / 128, (KDIM + 31) / 32);
    k_transpose_out<<<gc, 256>>>(out, N, NP);
}

// round 17
// speedup vs baseline: 1.1231x; 1.1231x over previous
#include <cuda_runtime.h>

#define CC    10
#define NBIN  49
#define HH    34
#define WW    34
#define HW    (HH * WW)          // 1156
#define KDIM  (CC * NBIN)        // 490
#define NMAX  30000
#define BLK   512
#define TILES 4
#define KPAD  512                // padded k rows (>= 16*32)
#define NPADMAX (NMAX + 128)
#define SLC   (NBIN * HW)        // 56644
#define RSTR  12                 // record stride in floats (48B)
#define SMEMB (HW * RSTR * 4)    // 55488 B dynamic smem

// Scratch (static device allocations are allowed)
__device__ float g_out_t[KPAD * NPADMAX];    // [k][n] with runtime pitch NP
__device__ float g_ftr[NBIN * HW * RSTR];    // [bin][pos][c0..9, pad2], 48B recs

// ---------------------------------------------------------------------------
// Kernel A: ft (C*49, 34, 34) -> 48B channel-interleaved per-bin records.
// 3 threads per record (c0-3 / c4-7 / c8-9). 48B stride => LDS.128 start
// bank-quad = (3*pos) mod 8 covers ALL 8 quads (conflict spread in k_roi).
// ---------------------------------------------------------------------------
__global__ void k_prep(const float* __restrict__ ft) {
    int t = blockIdx.x * blockDim.x + threadIdx.x;   // over 3*49*1156
    if (t >= 3 * SLC) return;
    int g   = t / SLC;                // 0,1,2
    int idx = t - g * SLC;            // = bin*HW + p
    const float* s = ft + idx;
    float* d = g_ftr + idx * RSTR;
    if (g == 0) {
        float4 v;
        v.x = s[0 * SLC]; v.y = s[1 * SLC]; v.z = s[2 * SLC]; v.w = s[3 * SLC];
        *reinterpret_cast<float4*>(d + 0) = v;
    } else if (g == 1) {
        float4 v;
        v.x = s[4 * SLC]; v.y = s[5 * SLC]; v.z = s[6 * SLC]; v.w = s[7 * SLC];
        *reinterpret_cast<float4*>(d + 4) = v;
    } else {
        float2 v;
        v.x = s[8 * SLC]; v.y = s[9 * SLC];
        *reinterpret_cast<float2*>(d + 8) = v;
    }
}

// ---------------------------------------------------------------------------
// Kernel B: one block = (bin, 4 roi-tiles of 512), grid (15, 49), 3 CTAs/SM.
// Dynamic smem: 1156 x 48B records. Interior fast path: 0<=wstart<=31 &&
// 0<=hstart<=31 => all taps in bounds, cnt=16, no bad11, floor-X0 in {0,1}.
// ---------------------------------------------------------------------------
__global__ __launch_bounds__(BLK, 3) void k_roi(const float* __restrict__ rois,
                                                int N, int NP) {
    extern __shared__ float smR[];   // [pos][12]
    const int bin = blockIdx.y;

    {   // stage: contiguous float4 copy, conflict-free
        const float4* s = reinterpret_cast<const float4*>(g_ftr + bin * HW * RSTR);
        float4* d = reinterpret_cast<float4*>(smR);
        for (int i = threadIdx.x; i < HW * (RSTR / 4); i += BLK) d[i] = s[i];
    }
    __syncthreads();

    const int ph = bin / 7, pw = bin % 7;

#pragma unroll 1
    for (int tile = 0; tile < TILES; tile++) {
        const int n = (blockIdx.x * TILES + tile) * BLK + threadIdx.x;
        if (n >= N) break;

        float rsw = __ldg(rois + n * 5 + 1) * 0.125f;
        float rsh = __ldg(rois + n * 5 + 2) * 0.125f;
        float rew = __ldg(rois + n * 5 + 3) * 0.125f;
        float reh = __ldg(rois + n * 5 + 4) * 0.125f;
        float rh = reh - rsh; rh = (rh > 0.1f) ? rh : 0.1f;
        float rw = rew - rsw; rw = (rw > 0.1f) ? rw : 0.1f;
        float bsh = rh * (1.f / 7.f), bsw = rw * (1.f / 7.f);
        float sub_h = bsh * 0.25f, sub_w = bsw * 0.25f;
        float hstart = floorf(rsh + (float)ph * bsh);
        float wstart = floorf(rsw + (float)pw * bsw);

        const int X0 = (int)fminf(fmaxf(wstart, 0.f), (float)(WW - 3));
        const int Y0 = (int)fminf(fmaxf(hstart, 0.f), (float)(HH - 3));

        float W00, W01, W02, W10, W11, W12, W20, W21, W22;
        bool colx, rowx;

        bool interior = (wstart >= 0.f) && (wstart <= 31.f) &&
                        (hstart >= 0.f) && (hstart <= 31.f);

        if (interior) {
            // ---------- FAST PATH ------------------------------------------
            float Y0f = (float)Y0, X0f = (float)X0;
            float wyA0 = 0.f, wyA1 = 0.f, wyA2 = 0.f;
#pragma unroll
            for (int ih = 0; ih < 4; ih++) {
                float h = fmaf((float)ih + 0.5f, sub_h, hstart);
                float y1f = floorf(h);
                float dy = h - y1f;
                bool r1 = (y1f != Y0f);            // r==1 (else r==0)
                float ay = 1.f - dy;
                wyA0 += r1 ? 0.f : ay;
                wyA1 += r1 ? ay  : dy;
                wyA2 += r1 ? dy  : 0.f;
            }
            float wxA0 = 0.f, wxA1 = 0.f, wxA2 = 0.f;
#pragma unroll
            for (int iw = 0; iw < 4; iw++) {
                float w = fmaf((float)iw + 0.5f, sub_w, wstart);
                float x1f = floorf(w);
                float dx = w - x1f;
                bool r1 = (x1f != X0f);
                float ax = 1.f - dx;
                wxA0 += r1 ? 0.f : ax;
                wxA1 += r1 ? ax  : dx;
                wxA2 += r1 ? dx  : 0.f;
            }
            const float inv = 1.f / 16.f;
            float wy0 = wyA0 * inv, wy1 = wyA1 * inv, wy2 = wyA2 * inv;
            W00 = wy0 * wxA0; W01 = wy0 * wxA1; W02 = wy0 * wxA2;
            W10 = wy1 * wxA0; W11 = wy1 * wxA1; W12 = wy1 * wxA2;
            W20 = wy2 * wxA0; W21 = wy2 * wxA1; W22 = wy2 * wxA2;
            colx = (wxA2 != 0.f);
            rowx = (wyA2 != 0.f);
        } else {
            // ---------- EDGE PATH: full reference logic (rare) --------------
            float WY0 = 0.f, WY1 = 0.f, WY2 = 0.f;
            float CY0 = 0.f, CY1 = 0.f, CY2 = 0.f;
            float cntY = 0.f;
#pragma unroll
            for (int ih = 0; ih < 4; ih++) {
                float h = hstart + ((float)ih + 0.5f) * sub_h;
                bool hok = (h > -1.f) && (h < (float)HH);
                float y1f = floorf(h), y2f = ceilf(h);
                bool yv = ((y1f >= 0.f) && (y1f < (float)HH)) ||
                          ((y2f >= 0.f) && (y2f < (float)HH));
                float y1c = fminf(fmaxf(y1f, 0.f), 33.f);
                float y2c = fminf(fmaxf(y2f, 0.f), 33.f);
                float dy = h - y1c;
                int ry1 = (int)y1c - Y0;
                int ry2 = (int)y2c - Y0;
                float hokf = hok ? 1.f : 0.f;
                cntY += hokf;
                float ay = hokf * (1.f - dy), by = hokf * dy;
                WY0 += ((ry1 == 0) ? ay : 0.f) + ((ry2 == 0) ? by : 0.f);
                WY1 += ((ry1 == 1) ? ay : 0.f) + ((ry2 == 1) ? by : 0.f);
                WY2 += ((ry1 == 2) ? ay : 0.f) + ((ry2 == 2) ? by : 0.f);
                float cy = (hok && yv) ? (1.f - dy) : 0.f;
                CY0 += (ry1 == 0) ? cy : 0.f;
                CY1 += (ry1 == 1) ? cy : 0.f;
                CY2 += (ry1 == 2) ? cy : 0.f;
            }
            float WX0 = 0.f, WX1 = 0.f, WX2 = 0.f;
            float CX0 = 0.f, CX1 = 0.f, CX2 = 0.f;
            float cntX = 0.f;
#pragma unroll
            for (int iw = 0; iw < 4; iw++) {
                float w = wstart + ((float)iw + 0.5f) * sub_w;
                bool wok = (w > -1.f) && (w < (float)WW);
                float x1f = floorf(w), x2f = ceilf(w);
                bool badx = !((x1f >= 0.f) && (x1f < (float)WW)) ||
                            !((x2f >= 0.f) && (x2f < (float)WW));
                float x1c = fminf(fmaxf(x1f, 0.f), 33.f);
                float x2c = fminf(fmaxf(x2f, 0.f), 33.f);
                float dx = w - x1c;
                int cx1 = (int)x1c - X0;
                int cx2 = (int)x2c - X0;
                float wokf = wok ? 1.f : 0.f;
                cntX += wokf;
                float ax = wokf * (1.f - dx), bx = wokf * dx;
                WX0 += ((cx1 == 0) ? ax : 0.f) + ((cx2 == 0) ? bx : 0.f);
                WX1 += ((cx1 == 1) ? ax : 0.f) + ((cx2 == 1) ? bx : 0.f);
                WX2 += ((cx1 == 2) ? ax : 0.f) + ((cx2 == 2) ? bx : 0.f);
                float cx = (wok && badx) ? (1.f - dx) : 0.f;
                CX0 += (cx1 == 0) ? cx : 0.f;
                CX1 += (cx1 == 1) ? cx : 0.f;
                CX2 += (cx1 == 2) ? cx : 0.f;
            }
            float cnt = cntY * cntX;
            float inv = (cnt > 0.f) ? (1.f / cnt) : 1.f;
            float wy0 = WY0 * inv, wy1 = WY1 * inv, wy2 = WY2 * inv;
            W00 = fmaf(wy0, WX0, -CY0 * CX0 * inv);
            W01 = fmaf(wy0, WX1, -CY0 * CX1 * inv);
            W02 = fmaf(wy0, WX2, -CY0 * CX2 * inv);
            W10 = fmaf(wy1, WX0, -CY1 * CX0 * inv);
            W11 = fmaf(wy1, WX1, -CY1 * CX1 * inv);
            W12 = fmaf(wy1, WX2, -CY1 * CX2 * inv);
            W20 = fmaf(wy2, WX0, -CY2 * CX0 * inv);
            W21 = fmaf(wy2, WX1, -CY2 * CX1 * inv);
            W22 = fmaf(wy2, WX2, -CY2 * CX2 * inv);
            colx = (W02 != 0.f) || (W12 != 0.f) || (W22 != 0.f);
            rowx = (W20 != 0.f) || (W21 != 0.f) || (W22 != 0.f);
        }

        // ---- apply stencil from 48B records ----
        float a0=0.f,a1=0.f,a2=0.f,a3=0.f,a4=0.f,a5=0.f,a6=0.f,a7=0.f,a8=0.f,a9=0.f;
        const int pbase = Y0 * WW + X0;

#define TEXEL(WGT, P) do {                                                  \
            const float* _t = smR + (P) * RSTR;                             \
            float4 u0 = *reinterpret_cast<const float4*>(_t);               \
            float4 u1 = *reinterpret_cast<const float4*>(_t + 4);           \
            float2 u2 = *reinterpret_cast<const float2*>(_t + 8);           \
            a0 = fmaf((WGT), u0.x, a0); a1 = fmaf((WGT), u0.y, a1);         \
            a2 = fmaf((WGT), u0.z, a2); a3 = fmaf((WGT), u0.w, a3);         \
            a4 = fmaf((WGT), u1.x, a4); a5 = fmaf((WGT), u1.y, a5);         \
            a6 = fmaf((WGT), u1.z, a6); a7 = fmaf((WGT), u1.w, a7);         \
            a8 = fmaf((WGT), u2.x, a8); a9 = fmaf((WGT), u2.y, a9);         \
        } while (0)

        TEXEL(W00, pbase);
        TEXEL(W01, pbase + 1);
        TEXEL(W10, pbase + WW);
        TEXEL(W11, pbase + WW + 1);
        if (colx) { TEXEL(W02, pbase + 2); TEXEL(W12, pbase + WW + 2); }
        if (rowx) { TEXEL(W20, pbase + 2 * WW); TEXEL(W21, pbase + 2 * WW + 1); }
        if (colx && rowx) { TEXEL(W22, pbase + 2 * WW + 2); }
#undef TEXEL

        // Coalesced store to scratch [c*49+bin][n] with pitch NP
        g_out_t[(0 * NBIN + bin) * NP + n] = a0;
        g_out_t[(1 * NBIN + bin) * NP + n] = a1;
        g_out_t[(2 * NBIN + bin) * NP + n] = a2;
        g_out_t[(3 * NBIN + bin) * NP + n] = a3;
        g_out_t[(4 * NBIN + bin) * NP + n] = a4;
        g_out_t[(5 * NBIN + bin) * NP + n] = a5;
        g_out_t[(6 * NBIN + bin) * NP + n] = a6;
        g_out_t[(7 * NBIN + bin) * NP + n] = a7;
        g_out_t[(8 * NBIN + bin) * NP + n] = a8;
        g_out_t[(9 * NBIN + bin) * NP + n] = a9;
    }
}

// ---------------------------------------------------------------------------
// Kernel C: transpose scratch[k][n] -> out[n][k]. Tile 32k x 128n, 256 thr.
// Loads UNGUARDED (k padded to KPAD, n padded to pitch NP), MLP=4.
// Output uses streaming stores (__stwt): out is write-once, never re-read,
// so bypass L2 write-allocate and keep scratch reads L2-resident.
// ---------------------------------------------------------------------------
__global__ __launch_bounds__(256) void k_transpose_out(float* __restrict__ out,
                                                       int N, int NP) {
    __shared__ float tile[32][133];
    const int n0 = blockIdx.x * 128;
    const int k0 = blockIdx.y * 32;
    const int tx = threadIdx.x & 31;     // n: 32 x float4 = 128
    const int ty = threadIdx.x >> 5;     // k: 8 rows per iter

#pragma unroll
    for (int i = 0; i < 4; i++) {
        int k = k0 + ty + 8 * i;
        float4 v = *reinterpret_cast<const float4*>(&g_out_t[(size_t)k * NP + n0 + tx * 4]);
        tile[ty + 8 * i][tx * 4 + 0] = v.x;
        tile[ty + 8 * i][tx * 4 + 1] = v.y;
        tile[ty + 8 * i][tx * 4 + 2] = v.z;
        tile[ty + 8 * i][tx * 4 + 3] = v.w;
    }
    __syncthreads();

    const int sx = threadIdx.x & 15;     // k: 16 x float2 = 32
    const int sy = threadIdx.x >> 4;     // n: 16 rows per iter
    const int k  = k0 + sx * 2;
    if (k < KDIM) {                       // KDIM even -> k+1 also in range
#pragma unroll
        for (int i = 0; i < 8; i++) {
            int n = n0 + sy + 16 * i;
            if (n < N) {
                float2 v;
                v.x = tile[sx * 2 + 0][sy + 16 * i];
                v.y = tile[sx * 2 + 1][sy + 16 * i];
                __stwt(reinterpret_cast<float2*>(&out[(size_t)n * KDIM + k]), v);
            }
        }
    }
}

// ---------------------------------------------------------------------------
extern "C" void kernel_launch(void* const* d_in, const int* in_sizes, int n_in,
                              void* d_out, int out_size) {
    const float* ft   = (const float*)d_in[0];
    const float* rois = (const float*)d_in[1];
    float*       out  = (float*)d_out;
    int N = in_sizes[1] / 5;
    if (N > NMAX) N = NMAX;
    if (N <= 0) return;
    int NP = (N + 127) & ~127;           // 128-aligned pitch

    // Opt in to >48KB dynamic smem for k_roi (attribute call, not an alloc;
    // idempotent and capture-legal).
    cudaFuncSetAttribute(k_roi, cudaFuncAttributeMaxDynamicSharedMemorySize, SMEMB);

    k_prep<<<(3 * SLC + 255) / 256, 256>>>(ft);

    dim3 gb((N + BLK * TILES - 1) / (BLK * TILES), NBIN);
    k_roi<<<gb, BLK, SMEMB>>>(rois, N, NP);

    dim3 gc(NP / 128, (KDIM + 31) / 32);
    k_transpose_out<<<gc, 256>>>(out, N, NP);
}